// round 1
// baseline (speedup 1.0000x reference)
#include <cuda_runtime.h>
#include <math.h>

// Problem constants
#define HEI   256
#define WID   256
#define HW    65536          // 256*256
#define CIN   192
#define C3    576            // 3*CIN
#define NB    4
#define NHEADS 8
#define HDIM  24
#define KDIM  192            // GEMM K for both big GEMMs

// ---------------- device scratch (static; no allocs allowed) ----------------
__device__ float g_qkv [(size_t)NB * C3 * HW];   // after 1x1 conv
__device__ float g_qkvd[(size_t)NB * C3 * HW];   // after depthwise 3x3
__device__ float g_gram[NB * NHEADS * HDIM * HDIM];
__device__ float g_sums[NB * 2 * CIN];           // per batch: [0,192) q sumsq, [192,384) k sumsq
__device__ float g_M   [NB * CIN * CIN];         // fused proj * blockdiag(attn)

// ---------------- zero small accumulators ----------------
__global__ void zero_small_kernel() {
    int i = blockIdx.x * 256 + threadIdx.x;
    if (i < NB * NHEADS * HDIM * HDIM) g_gram[i] = 0.0f;
    if (i < NB * 2 * CIN)              g_sums[i] = 0.0f;
}

// ---------------- tiled fp32 GEMM: C[M,N] = A[M,K] * B[K,N] ----------------
// BM=64, BN=128, BK=16, 256 threads, per-thread 4x8.
// MODE 0: qkv = qkv_w @ x      (A=ext weights shared across batch, B=ext x, C=g_qkv)
// MODE 1: out = M   @ v        (A=g_M per batch, B=g_qkvd v-part, C=ext out)
template <int MODE>
__global__ void __launch_bounds__(256) gemm64x128_kernel(
    const float* __restrict__ ext_b, const float* __restrict__ ext_a,
    float* __restrict__ ext_out)
{
    const int bz = blockIdx.z;
    const float* A;
    const float* B;
    float* C;
    if (MODE == 0) {
        A = ext_a;                                          // [576,192]
        B = ext_b + (size_t)bz * CIN * HW;                  // x[b]
        C = g_qkv + (size_t)bz * C3 * HW;
    } else {
        A = g_M   + (size_t)bz * CIN * CIN;                 // [192,192]
        B = g_qkvd + (size_t)bz * C3 * HW + (size_t)2 * CIN * HW; // v channels
        C = ext_out + (size_t)bz * CIN * HW;
    }

    const int n0 = blockIdx.x * 128;
    const int m0 = blockIdx.y * 64;
    const int tid = threadIdx.x;

    __shared__ float As[16][64];
    __shared__ float Bs[16][128];

    const int tr = tid >> 4;    // 0..15 (row group of 4)
    const int tc = tid & 15;    // 0..15 (col group of 8)

    float acc[4][8];
#pragma unroll
    for (int i = 0; i < 4; i++)
#pragma unroll
        for (int j = 0; j < 8; j++) acc[i][j] = 0.0f;

    const int am  = tid >> 2;          // 0..63
    const int akq = (tid & 3) * 4;     // 0,4,8,12

    for (int k0 = 0; k0 < KDIM; k0 += 16) {
        float4 a4 = *(const float4*)&A[(size_t)(m0 + am) * KDIM + k0 + akq];
        const int i0 = tid, i1 = tid + 256;
        float4 b0 = *(const float4*)&B[(size_t)(k0 + (i0 >> 5)) * HW + n0 + (i0 & 31) * 4];
        float4 b1 = *(const float4*)&B[(size_t)(k0 + (i1 >> 5)) * HW + n0 + (i1 & 31) * 4];
        __syncthreads();
        As[akq + 0][am] = a4.x;
        As[akq + 1][am] = a4.y;
        As[akq + 2][am] = a4.z;
        As[akq + 3][am] = a4.w;
        *(float4*)&Bs[i0 >> 5][(i0 & 31) * 4] = b0;
        *(float4*)&Bs[i1 >> 5][(i1 & 31) * 4] = b1;
        __syncthreads();
#pragma unroll
        for (int kk = 0; kk < 16; kk++) {
            float4 av  = *(const float4*)&As[kk][tr * 4];
            float4 bv0 = *(const float4*)&Bs[kk][tc * 8];
            float4 bv1 = *(const float4*)&Bs[kk][tc * 8 + 4];
            float a[4] = {av.x, av.y, av.z, av.w};
            float b[8] = {bv0.x, bv0.y, bv0.z, bv0.w, bv1.x, bv1.y, bv1.z, bv1.w};
#pragma unroll
            for (int i = 0; i < 4; i++)
#pragma unroll
                for (int j = 0; j < 8; j++) acc[i][j] = fmaf(a[i], b[j], acc[i][j]);
        }
    }

#pragma unroll
    for (int i = 0; i < 4; i++) {
        size_t row = (size_t)(m0 + tr * 4 + i) * HW + n0 + tc * 8;
        float4 o0 = {acc[i][0], acc[i][1], acc[i][2], acc[i][3]};
        float4 o1 = {acc[i][4], acc[i][5], acc[i][6], acc[i][7]};
        *(float4*)&C[row]     = o0;
        *(float4*)&C[row + 4] = o1;
    }
}

// ---------------- depthwise 3x3, pad=1 (cross-correlation, matches XLA/torch) ----------------
// block: (b*C3) x 32 strips of 8 rows; 256 threads = one full row width
__global__ void __launch_bounds__(256) dwconv3x3_kernel(const float* __restrict__ w)
{
    const int bc = blockIdx.x;               // b*C3 + c
    const int c  = bc % C3;
    const float* ip = g_qkv  + (size_t)bc * HW;
    float*       op = g_qkvd + (size_t)bc * HW;

    __shared__ float s[10][258];
    const int tid = threadIdx.x;
    const int y0  = blockIdx.y * 8;

#pragma unroll
    for (int r = 0; r < 10; r++) {
        int y = y0 + r - 1;
        s[r][tid + 1] = (y >= 0 && y < HEI) ? ip[y * WID + tid] : 0.0f;
    }
    if (tid < 10) { s[tid][0] = 0.0f; s[tid][257] = 0.0f; }

    float wr[9];
#pragma unroll
    for (int i = 0; i < 9; i++) wr[i] = w[c * 9 + i];
    __syncthreads();

#pragma unroll
    for (int r = 0; r < 8; r++) {
        float acc = 0.0f;
#pragma unroll
        for (int dy = 0; dy < 3; dy++)
#pragma unroll
            for (int dx = 0; dx < 3; dx++)
                acc = fmaf(s[r + dy][tid + dx], wr[dy * 3 + dx], acc);
        op[(y0 + r) * WID + tid] = acc;
    }
}

// ---------------- per-channel sum of squares for q,k (for L2 normalize) ----------------
__global__ void __launch_bounds__(256) sumsq_kernel()
{
    const int idx = blockIdx.x;              // b*384 + c', c' in [0,384)
    const int b = idx / (2 * CIN);
    const int cp = idx % (2 * CIN);
    const float* p = g_qkvd + ((size_t)b * C3 + cp) * HW;   // q then k channels

    float s = 0.0f;
    const float4* p4 = (const float4*)p;
    for (int i = threadIdx.x; i < HW / 4; i += 256) {
        float4 v = p4[i];
        s += v.x * v.x + v.y * v.y + v.z * v.z + v.w * v.w;
    }
    // block reduce
    __shared__ float sh[8];
    int lane = threadIdx.x & 31, wrp = threadIdx.x >> 5;
#pragma unroll
    for (int o = 16; o; o >>= 1) s += __shfl_down_sync(0xffffffffu, s, o);
    if (lane == 0) sh[wrp] = s;
    __syncthreads();
    if (threadIdx.x == 0) {
        float t = 0.0f;
#pragma unroll
        for (int w2 = 0; w2 < 8; w2++) t += sh[w2];
        g_sums[idx] = t;
    }
}

// ---------------- gram: G[b,h,d,e] = sum_n q[d,n]*k[e,n] ----------------
// grid: (8 chunks of 8192 n, 9 tiles of 8x8, NB*NHEADS)
#define GCHUNKS 8
__global__ void __launch_bounds__(256) gram_kernel()
{
    const int bh = blockIdx.z;
    const int b = bh >> 3, h = bh & 7;
    const int tile = blockIdx.y;
    const int d0 = (tile / 3) * 8, e0 = (tile % 3) * 8;
    const int nbeg = blockIdx.x * (HW / GCHUNKS);
    const int nend = nbeg + (HW / GCHUNKS);

    const float* qb = g_qkvd + ((size_t)b * C3 + h * HDIM + d0) * HW;
    const float* kb = g_qkvd + ((size_t)b * C3 + CIN + h * HDIM + e0) * HW;

    float acc[8][8];
#pragma unroll
    for (int i = 0; i < 8; i++)
#pragma unroll
        for (int j = 0; j < 8; j++) acc[i][j] = 0.0f;

    for (int n = nbeg + threadIdx.x; n < nend; n += 256) {
        float qv[8], kv[8];
#pragma unroll
        for (int i = 0; i < 8; i++) qv[i] = qb[(size_t)i * HW + n];
#pragma unroll
        for (int j = 0; j < 8; j++) kv[j] = kb[(size_t)j * HW + n];
#pragma unroll
        for (int i = 0; i < 8; i++)
#pragma unroll
            for (int j = 0; j < 8; j++) acc[i][j] = fmaf(qv[i], kv[j], acc[i][j]);
    }

    __shared__ float red[8][64];
    const int lane = threadIdx.x & 31, wrp = threadIdx.x >> 5;
#pragma unroll
    for (int i = 0; i < 8; i++) {
#pragma unroll
        for (int j = 0; j < 8; j++) {
            float v = acc[i][j];
#pragma unroll
            for (int o = 16; o; o >>= 1) v += __shfl_down_sync(0xffffffffu, v, o);
            if (lane == 0) red[wrp][i * 8 + j] = v;
        }
    }
    __syncthreads();
    if (threadIdx.x < 64) {
        float v = 0.0f;
#pragma unroll
        for (int w2 = 0; w2 < 8; w2++) v += red[w2][threadIdx.x];
        int i = threadIdx.x >> 3, j = threadIdx.x & 7;
        atomicAdd(&g_gram[((b * NHEADS + h) * HDIM + d0 + i) * HDIM + e0 + j], v);
    }
}

// ---------------- attn softmax + fold projection: M = proj * blockdiag(attn) ----------------
// grid (NHEADS, NB), 256 threads
__global__ void __launch_bounds__(256) attn_proj_kernel(
    const float* __restrict__ temp, const float* __restrict__ projw)
{
    const int h = blockIdx.x, b = blockIdx.y;
    __shared__ float attn[HDIM][HDIM];
    __shared__ float nq[HDIM], nk[HDIM];
    const int tid = threadIdx.x;

    if (tid < HDIM) {
        nq[tid] = fmaxf(sqrtf(g_sums[b * 2 * CIN + h * HDIM + tid]), 1e-12f);
        nk[tid] = fmaxf(sqrtf(g_sums[b * 2 * CIN + CIN + h * HDIM + tid]), 1e-12f);
    }
    __syncthreads();

    if (tid < HDIM) {
        const float t = temp[h];
        const float* g = g_gram + ((b * NHEADS + h) * HDIM + tid) * HDIM;
        float row[HDIM];
        float mx = -1e30f;
        const float inq = 1.0f / nq[tid];
#pragma unroll
        for (int e = 0; e < HDIM; e++) {
            row[e] = g[e] * t * inq / nk[e];
            mx = fmaxf(mx, row[e]);
        }
        float ssum = 0.0f;
#pragma unroll
        for (int e = 0; e < HDIM; e++) { row[e] = expf(row[e] - mx); ssum += row[e]; }
        const float inv = 1.0f / ssum;
#pragma unroll
        for (int e = 0; e < HDIM; e++) attn[tid][e] = row[e] * inv;
    }
    __syncthreads();

    // M[o, h*24+e] = sum_d projw[o, h*24+d] * attn[d][e]
    for (int idx = tid; idx < CIN * HDIM; idx += 256) {
        const int o = idx / HDIM, e = idx % HDIM;
        float s = 0.0f;
#pragma unroll
        for (int d = 0; d < HDIM; d++)
            s = fmaf(projw[o * CIN + h * HDIM + d], attn[d][e], s);
        g_M[(size_t)b * CIN * CIN + o * CIN + h * HDIM + e] = s;
    }
}

// ---------------- launch ----------------
extern "C" void kernel_launch(void* const* d_in, const int* in_sizes, int n_in,
                              void* d_out, int out_size)
{
    const float *x = nullptr, *qkvw = nullptr, *dww = nullptr, *projw = nullptr, *temp = nullptr;
    for (int i = 0; i < n_in; i++) {
        switch (in_sizes[i]) {
            case NB * CIN * HW:   x     = (const float*)d_in[i]; break;  // 50331648
            case C3 * CIN:        qkvw  = (const float*)d_in[i]; break;  // 110592
            case C3 * 9:          dww   = (const float*)d_in[i]; break;  // 5184
            case CIN * CIN:       projw = (const float*)d_in[i]; break;  // 36864
            case NHEADS:          temp  = (const float*)d_in[i]; break;  // 8
        }
    }
    float* out = (float*)d_out;

    zero_small_kernel<<<72, 256>>>();

    // 1x1 qkv conv: [576,192] @ [192,65536] per batch
    gemm64x128_kernel<0><<<dim3(HW / 128, C3 / 64, NB), 256>>>(x, qkvw, nullptr);

    // depthwise 3x3
    dwconv3x3_kernel<<<dim3(NB * C3, HEI / 8), 256>>>(dww);

    // norms + gram
    sumsq_kernel<<<NB * 2 * CIN, 256>>>();
    gram_kernel<<<dim3(GCHUNKS, 9, NB * NHEADS), 256>>>();

    // softmax + fold projection into per-batch M
    attn_proj_kernel<<<dim3(NHEADS, NB), 256>>>(temp, projw);

    // final: out = M @ v  ([192,192] @ [192,65536] per batch)
    gemm64x128_kernel<1><<<dim3(HW / 128, CIN / 64, NB), 256>>>(nullptr, nullptr, out);
}

// round 3
// speedup vs baseline: 5.0294x; 5.0294x over previous
#include <cuda_runtime.h>
#include <math.h>
#include <stdint.h>

// Problem constants
#define HEI   256
#define WID   256
#define HW    65536
#define CIN   192
#define C3    576
#define NB    4
#define NHEADS 8
#define HDIM  24

// ---------------- device scratch ----------------
__device__ __align__(256) float g_qkv [(size_t)NB * C3 * HW];
__device__ __align__(256) float g_qkvd[(size_t)NB * C3 * HW];
__device__ __align__(256) float g_gram[NB * NHEADS * HDIM * HDIM];
__device__ __align__(256) float g_sums[NB * 2 * CIN];
__device__ __align__(256) float g_M   [NB * CIN * CIN];

__device__ __forceinline__ uint32_t to_tf32_bits(float x) {
    uint32_t y; asm("cvt.rna.tf32.f32 %0, %1;" : "=r"(y) : "f"(x)); return y;
}

// ---------------- zero small accumulators ----------------
__global__ void zero_small_kernel() {
    int i = blockIdx.x * 256 + threadIdx.x;
    if (i < NB * NHEADS * HDIM * HDIM) g_gram[i] = 0.0f;
    if (i < NB * 2 * CIN)              g_sums[i] = 0.0f;
}

// ---------------- tf32 mma.sync GEMM ----------------
// C[M=channels, N=pixels] = A[M,K] @ B[K,N], K=192.
// Block: BM=192, BN=128, BK=32, 256 thr = 8 warps (4M x 2N), warp tile 48x64.
// MODE 0: A = qkv_w rows (blockIdx.y*192..), B = x[b],       C = g_qkv
// MODE 1: A = g_M[b],                        B = v(g_qkvd),  C = out
#define BM 192
#define BN 128
#define BK 32
#define AS_STRIDE 36     // floats; 36%32=4 -> conflict-free frag loads, 16B aligned
#define BS_STRIDE 136    // floats; 136%32=8 -> conflict-free frag loads, 16B aligned
#define AS_FLOATS (BM * AS_STRIDE)          // 6912
#define BS_FLOATS (BK * BS_STRIDE)          // 4352
#define STAGE_FLOATS (AS_FLOATS + BS_FLOATS)
#define GEMM_SMEM_BYTES (2 * STAGE_FLOATS * 4)   // 90112

__device__ __forceinline__ void mma_tf32_16x8x8(
    float& c0, float& c1, float& c2, float& c3,
    uint32_t a0, uint32_t a1, uint32_t a2, uint32_t a3,
    uint32_t b0, uint32_t b1)
{
    asm volatile(
        "mma.sync.aligned.m16n8k8.row.col.f32.tf32.tf32.f32 "
        "{%0,%1,%2,%3}, {%4,%5,%6,%7}, {%8,%9}, {%0,%1,%2,%3};"
        : "+f"(c0), "+f"(c1), "+f"(c2), "+f"(c3)
        : "r"(a0), "r"(a1), "r"(a2), "r"(a3), "r"(b0), "r"(b1));
}

template <int MODE>
__global__ void __launch_bounds__(256) gemm_mma_kernel(
    const float* __restrict__ xin, const float* __restrict__ win, float* __restrict__ outp)
{
    extern __shared__ float smem[];
    const int tid  = threadIdx.x;
    const int b    = blockIdx.z;
    const int pix0 = blockIdx.x * BN;

    const float* Ag; const float* Bg; float* Cg;
    if (MODE == 0) {
        const int m0 = blockIdx.y * BM;
        Ag = win + (size_t)m0 * CIN;                       // [576,192] rows m0..
        Bg = xin + (size_t)b * CIN * HW;                   // x[b]: [192][HW]
        Cg = g_qkv + ((size_t)b * C3 + m0) * HW;
    } else {
        Ag = g_M + (size_t)b * CIN * CIN;                  // [192,192]
        Bg = g_qkvd + ((size_t)b * C3 + 2 * CIN) * HW;     // v channels
        Cg = outp + (size_t)b * CIN * HW;
    }

    const int warp  = tid >> 5;
    const int lane  = tid & 31;
    const int warpM = warp >> 1;      // 0..3
    const int warpN = warp & 1;       // 0..1
    const int m0w   = warpM * 48;
    const int n0w   = warpN * 64;
    const int g     = lane >> 2;      // 0..7
    const int cq    = lane & 3;       // 0..3

    // global load index precompute
    const int a_row = tid >> 3;              // +i*32 per chunk; (tid + i*256)>>3
    const int a_kq  = (tid & 7) * 4;
    const int b_kr  = tid >> 5;              // (tid + i*256)>>5 = b_kr + i*8
    const int b_n4  = (lane) * 4;

    float4 areg[6], breg[4];

    auto loadA = [&](int t) {
#pragma unroll
        for (int i = 0; i < 6; i++)
            areg[i] = *(const float4*)&Ag[(size_t)(a_row + i * 32) * CIN + t * BK + a_kq];
    };
    auto loadB = [&](int t) {
#pragma unroll
        for (int i = 0; i < 4; i++)
            breg[i] = *(const float4*)&Bg[(size_t)(t * BK + b_kr + i * 8) * HW + pix0 + b_n4];
    };
    auto storeA = [&](int s) {
        float* As = smem + s * STAGE_FLOATS;
#pragma unroll
        for (int i = 0; i < 6; i++) {
            uint32_t* p = (uint32_t*)&As[(a_row + i * 32) * AS_STRIDE + a_kq];
            p[0] = to_tf32_bits(areg[i].x); p[1] = to_tf32_bits(areg[i].y);
            p[2] = to_tf32_bits(areg[i].z); p[3] = to_tf32_bits(areg[i].w);
        }
    };
    auto storeB = [&](int s) {
        float* Bs = smem + s * STAGE_FLOATS + AS_FLOATS;
#pragma unroll
        for (int i = 0; i < 4; i++) {
            uint32_t* p = (uint32_t*)&Bs[(b_kr + i * 8) * BS_STRIDE + b_n4];
            p[0] = to_tf32_bits(breg[i].x); p[1] = to_tf32_bits(breg[i].y);
            p[2] = to_tf32_bits(breg[i].z); p[3] = to_tf32_bits(breg[i].w);
        }
    };

    float c[3][8][4];
#pragma unroll
    for (int i = 0; i < 3; i++)
#pragma unroll
        for (int j = 0; j < 8; j++)
#pragma unroll
            for (int q = 0; q < 4; q++) c[i][j][q] = 0.0f;

    loadA(0); loadB(0);
    storeA(0); storeB(0);
    __syncthreads();

#pragma unroll 1
    for (int t = 0; t < 6; t++) {
        if (t < 5) { loadA(t + 1); loadB(t + 1); }
        const int s = t & 1;
        const uint32_t* As = (const uint32_t*)(smem + s * STAGE_FLOATS);
        const uint32_t* Bs = (const uint32_t*)(smem + s * STAGE_FLOATS + AS_FLOATS);
#pragma unroll
        for (int kk = 0; kk < 4; kk++) {
            const int kb = kk * 8;
            uint32_t af[3][4], bf[8][2];
#pragma unroll
            for (int ms = 0; ms < 3; ms++) {
                const int mrow = m0w + ms * 16 + g;
                af[ms][0] = As[(mrow)     * AS_STRIDE + kb + cq];
                af[ms][1] = As[(mrow + 8) * AS_STRIDE + kb + cq];
                af[ms][2] = As[(mrow)     * AS_STRIDE + kb + cq + 4];
                af[ms][3] = As[(mrow + 8) * AS_STRIDE + kb + cq + 4];
            }
#pragma unroll
            for (int ns = 0; ns < 8; ns++) {
                const int ncol = n0w + ns * 8 + g;
                bf[ns][0] = Bs[(kb + cq)     * BS_STRIDE + ncol];
                bf[ns][1] = Bs[(kb + cq + 4) * BS_STRIDE + ncol];
            }
#pragma unroll
            for (int ms = 0; ms < 3; ms++)
#pragma unroll
                for (int ns = 0; ns < 8; ns++)
                    mma_tf32_16x8x8(c[ms][ns][0], c[ms][ns][1], c[ms][ns][2], c[ms][ns][3],
                                    af[ms][0], af[ms][1], af[ms][2], af[ms][3],
                                    bf[ns][0], bf[ns][1]);
        }
        if (t < 5) {
            storeA((t + 1) & 1); storeB((t + 1) & 1);
            __syncthreads();
        }
    }

    // epilogue: c regs -> global. row = m0w + ms*16 + g (+8), col = n0w + ns*8 + 2*cq (+1)
#pragma unroll
    for (int ms = 0; ms < 3; ms++) {
        const int m = m0w + ms * 16 + g;
#pragma unroll
        for (int ns = 0; ns < 8; ns++) {
            const int n = pix0 + n0w + ns * 8 + cq * 2;
            *(float2*)&Cg[(size_t)m * HW + n]       = make_float2(c[ms][ns][0], c[ms][ns][1]);
            *(float2*)&Cg[(size_t)(m + 8) * HW + n] = make_float2(c[ms][ns][2], c[ms][ns][3]);
        }
    }
}

// ---------------- depthwise 3x3 + fused per-channel sumsq ----------------
__global__ void __launch_bounds__(256) dwconv3x3_kernel(const float* __restrict__ w)
{
    const int bc = blockIdx.x;               // b*C3 + ch
    const int ch = bc % C3;
    const int b  = bc / C3;
    const float* ip = g_qkv  + (size_t)bc * HW;
    float*       op = g_qkvd + (size_t)bc * HW;

    __shared__ float s[34][258];
    const int tid = threadIdx.x;
    const int y0  = blockIdx.y * 32;

    for (int i = tid; i < 34 * 256; i += 256) {
        const int r = i >> 8, xc = i & 255;
        const int y = y0 + r - 1;
        s[r][xc + 1] = (y >= 0 && y < HEI) ? ip[y * WID + xc] : 0.0f;
    }
    if (tid < 34) { s[tid][0] = 0.0f; s[tid][257] = 0.0f; }

    float wr[9];
#pragma unroll
    for (int i = 0; i < 9; i++) wr[i] = w[ch * 9 + i];
    __syncthreads();

    float ssq = 0.0f;
#pragma unroll 4
    for (int r = 0; r < 32; r++) {
        float acc = 0.0f;
#pragma unroll
        for (int dy = 0; dy < 3; dy++)
#pragma unroll
            for (int dx = 0; dx < 3; dx++)
                acc = fmaf(s[r + dy][tid + dx], wr[dy * 3 + dx], acc);
        op[(y0 + r) * WID + tid] = acc;
        ssq = fmaf(acc, acc, ssq);
    }

    if (ch < 2 * CIN) {   // q or k channel -> accumulate L2 norm
        __shared__ float red[8];
        const int lane = tid & 31, wp = tid >> 5;
#pragma unroll
        for (int o = 16; o; o >>= 1) ssq += __shfl_down_sync(0xffffffffu, ssq, o);
        if (lane == 0) red[wp] = ssq;
        __syncthreads();
        if (tid == 0) {
            float t = 0.0f;
#pragma unroll
            for (int i = 0; i < 8; i++) t += red[i];
            atomicAdd(&g_sums[b * 2 * CIN + ch], t);
        }
    }
}

// ---------------- gram: G[b,h,d,e] = sum_n q[d,n]*k[e,n] ----------------
#define GCHUNKS 8
__global__ void __launch_bounds__(256) gram_kernel()
{
    const int bh = blockIdx.z;
    const int b = bh >> 3, h = bh & 7;
    const int tile = blockIdx.y;
    const int d0 = (tile / 3) * 8, e0 = (tile % 3) * 8;
    const int nbeg = blockIdx.x * (HW / GCHUNKS);
    const int nend = nbeg + (HW / GCHUNKS);

    const float* qb = g_qkvd + ((size_t)b * C3 + h * HDIM + d0) * HW;
    const float* kb = g_qkvd + ((size_t)b * C3 + CIN + h * HDIM + e0) * HW;

    float acc[8][8];
#pragma unroll
    for (int i = 0; i < 8; i++)
#pragma unroll
        for (int j = 0; j < 8; j++) acc[i][j] = 0.0f;

    for (int n = nbeg + threadIdx.x; n < nend; n += 256) {
        float qv[8], kv[8];
#pragma unroll
        for (int i = 0; i < 8; i++) qv[i] = qb[(size_t)i * HW + n];
#pragma unroll
        for (int j = 0; j < 8; j++) kv[j] = kb[(size_t)j * HW + n];
#pragma unroll
        for (int i = 0; i < 8; i++)
#pragma unroll
            for (int j = 0; j < 8; j++) acc[i][j] = fmaf(qv[i], kv[j], acc[i][j]);
    }

    __shared__ float red[8][64];
    const int lane = threadIdx.x & 31, wrp = threadIdx.x >> 5;
#pragma unroll
    for (int i = 0; i < 8; i++) {
#pragma unroll
        for (int j = 0; j < 8; j++) {
            float v = acc[i][j];
#pragma unroll
            for (int o = 16; o; o >>= 1) v += __shfl_down_sync(0xffffffffu, v, o);
            if (lane == 0) red[wrp][i * 8 + j] = v;
        }
    }
    __syncthreads();
    if (threadIdx.x < 64) {
        float v = 0.0f;
#pragma unroll
        for (int w2 = 0; w2 < 8; w2++) v += red[w2][threadIdx.x];
        const int i = threadIdx.x >> 3, j = threadIdx.x & 7;
        atomicAdd(&g_gram[((b * NHEADS + h) * HDIM + d0 + i) * HDIM + e0 + j], v);
    }
}

// ---------------- softmax + fold projection: M = proj * blockdiag(attn) ----------------
__global__ void __launch_bounds__(256) attn_proj_kernel(
    const float* __restrict__ temp, const float* __restrict__ projw)
{
    const int h = blockIdx.x, b = blockIdx.y;
    __shared__ float attn[HDIM][HDIM];
    __shared__ float nq[HDIM], nk[HDIM];
    const int tid = threadIdx.x;

    if (tid < HDIM) {
        nq[tid] = fmaxf(sqrtf(g_sums[b * 2 * CIN + h * HDIM + tid]), 1e-12f);
        nk[tid] = fmaxf(sqrtf(g_sums[b * 2 * CIN + CIN + h * HDIM + tid]), 1e-12f);
    }
    __syncthreads();

    if (tid < HDIM) {
        const float t = temp[h];
        const float* gg = g_gram + ((b * NHEADS + h) * HDIM + tid) * HDIM;
        float row[HDIM];
        float mx = -1e30f;
        const float inq = 1.0f / nq[tid];
#pragma unroll
        for (int e = 0; e < HDIM; e++) {
            row[e] = gg[e] * t * inq / nk[e];
            mx = fmaxf(mx, row[e]);
        }
        float ssum = 0.0f;
#pragma unroll
        for (int e = 0; e < HDIM; e++) { row[e] = expf(row[e] - mx); ssum += row[e]; }
        const float inv = 1.0f / ssum;
#pragma unroll
        for (int e = 0; e < HDIM; e++) attn[tid][e] = row[e] * inv;
    }
    __syncthreads();

    for (int idx = tid; idx < CIN * HDIM; idx += 256) {
        const int o = idx / HDIM, e = idx % HDIM;
        float ssum = 0.0f;
#pragma unroll
        for (int d = 0; d < HDIM; d++)
            ssum = fmaf(projw[o * CIN + h * HDIM + d], attn[d][e], ssum);
        g_M[(size_t)b * CIN * CIN + o * CIN + h * HDIM + e] = ssum;
    }
}

// ---------------- launch ----------------
extern "C" void kernel_launch(void* const* d_in, const int* in_sizes, int n_in,
                              void* d_out, int out_size)
{
    const float *x = nullptr, *qkvw = nullptr, *dww = nullptr, *projw = nullptr, *temp = nullptr;
    for (int i = 0; i < n_in; i++) {
        switch (in_sizes[i]) {
            case NB * CIN * HW:   x     = (const float*)d_in[i]; break;
            case C3 * CIN:        qkvw  = (const float*)d_in[i]; break;
            case C3 * 9:          dww   = (const float*)d_in[i]; break;
            case CIN * CIN:       projw = (const float*)d_in[i]; break;
            case NHEADS:          temp  = (const float*)d_in[i]; break;
        }
    }
    float* out = (float*)d_out;

    static int configured = 0;
    if (!configured) {
        cudaFuncSetAttribute(gemm_mma_kernel<0>, cudaFuncAttributeMaxDynamicSharedMemorySize, GEMM_SMEM_BYTES);
        cudaFuncSetAttribute(gemm_mma_kernel<1>, cudaFuncAttributeMaxDynamicSharedMemorySize, GEMM_SMEM_BYTES);
        configured = 1;
    }

    zero_small_kernel<<<72, 256>>>();

    // qkv 1x1 conv: [576,192] @ [192,65536] per batch, 3 channel tiles of 192
    gemm_mma_kernel<0><<<dim3(HW / BN, 3, NB), 256, GEMM_SMEM_BYTES>>>(x, qkvw, nullptr);

    // depthwise 3x3 (+ fused q/k sum-of-squares)
    dwconv3x3_kernel<<<dim3(NB * C3, HEI / 32), 256>>>(dww);

    // gram accumulators
    gram_kernel<<<dim3(GCHUNKS, 9, NB * NHEADS), 256>>>();

    // softmax + fold projection into per-batch M
    attn_proj_kernel<<<dim3(NHEADS, NB), 256>>>(temp, projw);

    // final: out = M @ v  ([192,192] @ [192,65536] per batch)
    gemm_mma_kernel<1><<<dim3(HW / BN, 1, NB), 256, GEMM_SMEM_BYTES>>>(nullptr, nullptr, out);
}